// round 4
// baseline (speedup 1.0000x reference)
#include <cuda_runtime.h>
#include <cstdint>
#include <math.h>

// Problem constants
#define B_  2
#define Q_  2048
#define KV_ 2048
#define D_  1024
#define H_  16
#define DH_ 64

#define TS 68   // padded row stride (floats) for 64-wide tf32 tiles

// ---------------------------------------------------------------------------
// Scratch (device globals — allocation-free per harness rules)
// ---------------------------------------------------------------------------
__device__ float g_qp[B_ * Q_ * D_];        // 16.8 MB  q projection
__device__ float g_kp[B_ * KV_ * D_];       // 16.8 MB  k projection
__device__ float g_attn[B_ * Q_ * KV_];     // 33.6 MB  head-averaged probs
__device__ float g_sum[B_ * H_ * Q_];       // 256 KB   per-(b,h,row) sumexp
__device__ float g_rscale[B_ * (Q_ + KV_)]; // 32 KB    per-row rmsnorm scale

// ---------------------------------------------------------------------------
// Helpers
// ---------------------------------------------------------------------------
__device__ __forceinline__ uint32_t f2tf(float x) {
    uint32_t r;
    asm("cvt.rna.tf32.f32 %0, %1;" : "=r"(r) : "f"(x));
    return r;
}

__device__ __forceinline__ void mma8(float* d, const uint32_t* a, const uint32_t* b) {
    asm volatile(
        "mma.sync.aligned.m16n8k8.row.col.f32.tf32.tf32.f32 "
        "{%0,%1,%2,%3}, {%4,%5,%6,%7}, {%8,%9}, {%0,%1,%2,%3};\n"
        : "+f"(d[0]), "+f"(d[1]), "+f"(d[2]), "+f"(d[3])
        : "r"(a[0]), "r"(a[1]), "r"(a[2]), "r"(a[3]), "r"(b[0]), "r"(b[1]));
}

// MMA over a K-range of a 128x128 tile held in smem (stride TS), warp layout:
// wm in {0,64}, wn in {0,32,64,96}; thread rows wm+mi*16+(lane>>2), +8.
template <int K0, int K1>
__device__ __forceinline__ void mma_range(const uint32_t* __restrict__ As,
                                          const uint32_t* __restrict__ Bs,
                                          float acc[4][4][4], int wm, int wn, int lane)
{
#pragma unroll
    for (int kk = K0; kk < K1; kk += 8) {
        uint32_t af[4][4], bf[4][2];
        int c0 = kk + (lane & 3);
#pragma unroll
        for (int mi = 0; mi < 4; mi++) {
            int r0 = wm + mi * 16 + (lane >> 2);
            af[mi][0] = As[r0 * TS + c0];
            af[mi][1] = As[(r0 + 8) * TS + c0];
            af[mi][2] = As[r0 * TS + c0 + 4];
            af[mi][3] = As[(r0 + 8) * TS + c0 + 4];
        }
#pragma unroll
        for (int ni = 0; ni < 4; ni++) {
            int n0 = wn + ni * 8 + (lane >> 2);
            bf[ni][0] = Bs[n0 * TS + c0];
            bf[ni][1] = Bs[n0 * TS + c0 + 4];
        }
#pragma unroll
        for (int mi = 0; mi < 4; mi++)
#pragma unroll
            for (int ni = 0; ni < 4; ni++)
                mma8(acc[mi][ni], af[mi], bf[ni]);
    }
}

// ---------------------------------------------------------------------------
// Kernel 1: per-row rmsnorm scale (q rows [0,4096), k rows [4096,8192))
// ---------------------------------------------------------------------------
__global__ __launch_bounds__(256) void rms_scale_kernel(
    const float* __restrict__ q, const float* __restrict__ k)
{
    __shared__ float red[8];
    int row = blockIdx.x, tid = threadIdx.x;
    const float* x = (row < B_ * Q_) ? q + (size_t)row * D_
                                     : k + (size_t)(row - B_ * Q_) * D_;
    float4 v = ((const float4*)x)[tid];
    float ss = v.x * v.x + v.y * v.y + v.z * v.z + v.w * v.w;
#pragma unroll
    for (int o = 16; o; o >>= 1) ss += __shfl_xor_sync(0xffffffffu, ss, o);
    if ((tid & 31) == 0) red[tid >> 5] = ss;
    __syncthreads();
    if (tid == 0) {
        float s2 = red[0] + red[1] + red[2] + red[3] + red[4] + red[5] + red[6] + red[7];
        g_rscale[row] = rsqrtf(s2 * (1.0f / (float)D_) + 1.1920928955078125e-07f);
    }
}

// ---------------------------------------------------------------------------
// Projection GEMM (NT) with fused rmsnorm: C = (X*rs_row*w_col) @ W^T + bias
// 128x128 tile, BK=32, tf32 mma.
// ---------------------------------------------------------------------------
#define BK 32

__global__ __launch_bounds__(256) void gemm_proj_kernel(
    const float* __restrict__ X, const float* __restrict__ W,
    const float* __restrict__ wnorm, const float* __restrict__ bias,
    const float* __restrict__ rs, float* __restrict__ C)
{
    __shared__ uint32_t As[128][BK + 4];
    __shared__ uint32_t Bs[128][BK + 4];

    int bm = blockIdx.y * 128;
    int bn = blockIdx.x * 128;
    int tid = threadIdx.x, lane = tid & 31, wid = tid >> 5;
    int wm = (wid >> 2) * 64;
    int wn = (wid & 3) * 32;

    float acc[4][4][4];
#pragma unroll
    for (int mi = 0; mi < 4; mi++)
#pragma unroll
        for (int ni = 0; ni < 4; ni++)
#pragma unroll
            for (int c = 0; c < 4; c++) acc[mi][ni][c] = 0.0f;

    for (int kt = 0; kt < D_; kt += BK) {
#pragma unroll
        for (int i = 0; i < 4; i++) {
            int f  = tid + i * 256;
            int r  = f >> 3;
            int c4 = (f & 7) << 2;
            float4 va = *(const float4*)(X + (size_t)(bm + r) * D_ + kt + c4);
            float s = rs[bm + r];
            float4 wv = *(const float4*)(wnorm + kt + c4);
            As[r][c4]     = f2tf(va.x * s * wv.x);
            As[r][c4 + 1] = f2tf(va.y * s * wv.y);
            As[r][c4 + 2] = f2tf(va.z * s * wv.z);
            As[r][c4 + 3] = f2tf(va.w * s * wv.w);
            float4 vb = *(const float4*)(W + (size_t)(bn + r) * D_ + kt + c4);
            Bs[r][c4]     = f2tf(vb.x);
            Bs[r][c4 + 1] = f2tf(vb.y);
            Bs[r][c4 + 2] = f2tf(vb.z);
            Bs[r][c4 + 3] = f2tf(vb.w);
        }
        __syncthreads();

#pragma unroll
        for (int kk = 0; kk < BK; kk += 8) {
            uint32_t af[4][4], bf[4][2];
            int c0 = kk + (lane & 3);
#pragma unroll
            for (int mi = 0; mi < 4; mi++) {
                int r0 = wm + mi * 16 + (lane >> 2);
                af[mi][0] = As[r0][c0];
                af[mi][1] = As[r0 + 8][c0];
                af[mi][2] = As[r0][c0 + 4];
                af[mi][3] = As[r0 + 8][c0 + 4];
            }
#pragma unroll
            for (int ni = 0; ni < 4; ni++) {
                int n0 = wn + ni * 8 + (lane >> 2);
                bf[ni][0] = Bs[n0][c0];
                bf[ni][1] = Bs[n0][c0 + 4];
            }
#pragma unroll
            for (int mi = 0; mi < 4; mi++)
#pragma unroll
                for (int ni = 0; ni < 4; ni++)
                    mma8(acc[mi][ni], af[mi], bf[ni]);
        }
        __syncthreads();
    }

#pragma unroll
    for (int mi = 0; mi < 4; mi++) {
        int r0 = bm + wm + mi * 16 + (lane >> 2);
#pragma unroll
        for (int ni = 0; ni < 4; ni++) {
            int c0 = bn + wn + ni * 8 + ((lane & 3) << 1);
            float b0 = bias[c0], b1 = bias[c0 + 1];
            C[(size_t)r0 * D_ + c0]           = acc[mi][ni][0] + b0;
            C[(size_t)r0 * D_ + c0 + 1]       = acc[mi][ni][1] + b1;
            C[(size_t)(r0 + 8) * D_ + c0]     = acc[mi][ni][2] + b0;
            C[(size_t)(r0 + 8) * D_ + c0 + 1] = acc[mi][ni][3] + b1;
        }
    }
}

// ---------------------------------------------------------------------------
// K1: sumexp. CTA per (q-tile, b*H). Q-tile A slice resident in smem; stream
// all 16 KV tiles with double-buffered B. s[b,h,i] = sum_j exp(score/8).
// ---------------------------------------------------------------------------
__global__ __launch_bounds__(256) void k1_sumexp_kernel()
{
    extern __shared__ float sm[];
    float* As   = sm;                    // 128*TS
    float* Bsb  = sm + 128 * TS;         // 2 * 128*TS
    float* rsum_sm = sm + 3 * 128 * TS;  // 128

    int tid = threadIdx.x, lane = tid & 31, wid = tid >> 5;
    int qb = blockIdx.x * 128;
    int z  = blockIdx.y;                 // b*16 + h
    int b  = z >> 4, h = z & 15;
    const float* A  = g_qp + (size_t)b * Q_ * D_  + h * DH_;
    const float* Bg = g_kp + (size_t)b * KV_ * D_ + h * DH_;

    // Load A tile (128 x 64) as tf32
#pragma unroll
    for (int i = 0; i < 8; i++) {
        int f = tid + i * 256, r = f >> 4, c = (f & 15) << 2;
        float4 v = *(const float4*)(A + (size_t)(qb + r) * D_ + c);
        uint32_t* p = (uint32_t*)(As + r * TS + c);
        p[0] = f2tf(v.x); p[1] = f2tf(v.y); p[2] = f2tf(v.z); p[3] = f2tf(v.w);
    }
    // Load B tile j=0 into buffer 0
#pragma unroll
    for (int i = 0; i < 8; i++) {
        int f = tid + i * 256, r = f >> 4, c = (f & 15) << 2;
        float4 v = *(const float4*)(Bg + (size_t)r * D_ + c);
        uint32_t* p = (uint32_t*)(Bsb + r * TS + c);
        p[0] = f2tf(v.x); p[1] = f2tf(v.y); p[2] = f2tf(v.z); p[3] = f2tf(v.w);
    }
    if (tid < 128) rsum_sm[tid] = 0.0f;
    __syncthreads();

    int wm = (wid >> 2) * 64;
    int wn = (wid & 3) * 32;

    float rsum[8];
#pragma unroll
    for (int i = 0; i < 8; i++) rsum[i] = 0.0f;

    for (int j = 0; j < 16; j++) {
        float4 rv[8];
        if (j < 15) {
            const float* Bn = Bg + (size_t)(j + 1) * 128 * D_;
#pragma unroll
            for (int i = 0; i < 8; i++) {
                int f = tid + i * 256, r = f >> 4, c = (f & 15) << 2;
                rv[i] = *(const float4*)(Bn + (size_t)r * D_ + c);
            }
        }

        const uint32_t* Bcur = (const uint32_t*)(Bsb + (j & 1) * 128 * TS);
        float acc[4][4][4];
#pragma unroll
        for (int mi = 0; mi < 4; mi++)
#pragma unroll
            for (int ni = 0; ni < 4; ni++)
#pragma unroll
                for (int c = 0; c < 4; c++) acc[mi][ni][c] = 0.0f;

        mma_range<0, 64>((const uint32_t*)As, Bcur, acc, wm, wn, lane);

#pragma unroll
        for (int mi = 0; mi < 4; mi++)
#pragma unroll
            for (int ni = 0; ni < 4; ni++) {
                rsum[2 * mi]     += __expf(acc[mi][ni][0] * 0.125f) + __expf(acc[mi][ni][1] * 0.125f);
                rsum[2 * mi + 1] += __expf(acc[mi][ni][2] * 0.125f) + __expf(acc[mi][ni][3] * 0.125f);
            }

        if (j < 15) {
            uint32_t* Bnx = (uint32_t*)(Bsb + ((j + 1) & 1) * 128 * TS);
#pragma unroll
            for (int i = 0; i < 8; i++) {
                int f = tid + i * 256, r = f >> 4, c = (f & 15) << 2;
                uint32_t* p = Bnx + r * TS + c;
                p[0] = f2tf(rv[i].x); p[1] = f2tf(rv[i].y);
                p[2] = f2tf(rv[i].z); p[3] = f2tf(rv[i].w);
            }
        }
        __syncthreads();
    }

    // reduce over the 4 lanes that share a row (lane&3)
#pragma unroll
    for (int i = 0; i < 8; i++) {
        rsum[i] += __shfl_xor_sync(0xffffffffu, rsum[i], 1);
        rsum[i] += __shfl_xor_sync(0xffffffffu, rsum[i], 2);
    }
    if ((lane & 3) == 0) {
#pragma unroll
        for (int mi = 0; mi < 4; mi++) {
            atomicAdd(&rsum_sm[wm + mi * 16 + (lane >> 2)],     rsum[2 * mi]);
            atomicAdd(&rsum_sm[wm + mi * 16 + (lane >> 2) + 8], rsum[2 * mi + 1]);
        }
    }
    __syncthreads();
    if (tid < 128) g_sum[(size_t)z * Q_ + qb + tid] = rsum_sm[tid];
}

// ---------------------------------------------------------------------------
// K2: attn. CTA per (kv-tile, q-tile, b). Loops 16 heads, recomputes scores,
// accumulates sum_h exp(score/8)/(16*s) in regs. Double-buffered A and B with
// a single reused 32-reg stage. Writes g_attn once.
// ---------------------------------------------------------------------------
__global__ __launch_bounds__(256) void k2_attn_kernel()
{
    extern __shared__ float sm[];
    float* Asb  = sm;                    // 2 * 128*TS
    float* Bsb  = sm + 2 * 128 * TS;     // 2 * 128*TS
    float* sinv = sm + 4 * 128 * TS;     // 16*128

    int tid = threadIdx.x, lane = tid & 31, wid = tid >> 5;
    int kb = blockIdx.x * 128;
    int qb = blockIdx.y * 128;
    int b  = blockIdx.z;
    const float* A0 = g_qp + (size_t)b * Q_ * D_;
    const float* B0 = g_kp + (size_t)b * KV_ * D_;

    // sinv[h][r] = 1 / (16 * sum)
#pragma unroll
    for (int i = 0; i < 8; i++) {
        int idx = tid + i * 256;
        int hh = idx >> 7, r = idx & 127;
        sinv[idx] = 1.0f / (16.0f * g_sum[(size_t)(b * 16 + hh) * Q_ + qb + r]);
    }
    // preload h=0 into buffers 0
#pragma unroll
    for (int i = 0; i < 8; i++) {
        int f = tid + i * 256, r = f >> 4, c = (f & 15) << 2;
        float4 va = *(const float4*)(A0 + (size_t)(qb + r) * D_ + c);
        uint32_t* pa = (uint32_t*)(Asb + r * TS + c);
        pa[0] = f2tf(va.x); pa[1] = f2tf(va.y); pa[2] = f2tf(va.z); pa[3] = f2tf(va.w);
        float4 vb = *(const float4*)(B0 + (size_t)(kb + r) * D_ + c);
        uint32_t* pb = (uint32_t*)(Bsb + r * TS + c);
        pb[0] = f2tf(vb.x); pb[1] = f2tf(vb.y); pb[2] = f2tf(vb.z); pb[3] = f2tf(vb.w);
    }
    __syncthreads();

    int wm = (wid >> 2) * 64;
    int wn = (wid & 3) * 32;

    float attn[4][4][4];
#pragma unroll
    for (int mi = 0; mi < 4; mi++)
#pragma unroll
        for (int ni = 0; ni < 4; ni++)
#pragma unroll
            for (int c = 0; c < 4; c++) attn[mi][ni][c] = 0.0f;

    for (int h = 0; h < 16; h++) {
        int cur = h & 1, nxt = cur ^ 1;
        const uint32_t* Acur = (const uint32_t*)(Asb + cur * 128 * TS);
        const uint32_t* Bcur = (const uint32_t*)(Bsb + cur * 128 * TS);

        float4 rv[8];
        if (h < 15) {  // issue A(h+1) loads
            const float* An = A0 + (h + 1) * DH_;
#pragma unroll
            for (int i = 0; i < 8; i++) {
                int f = tid + i * 256, r = f >> 4, c = (f & 15) << 2;
                rv[i] = *(const float4*)(An + (size_t)(qb + r) * D_ + c);
            }
        }

        float acc[4][4][4];
#pragma unroll
        for (int mi = 0; mi < 4; mi++)
#pragma unroll
            for (int ni = 0; ni < 4; ni++)
#pragma unroll
                for (int c = 0; c < 4; c++) acc[mi][ni][c] = 0.0f;

        mma_range<0, 32>(Acur, Bcur, acc, wm, wn, lane);

        if (h < 15) {  // store A(h+1), issue B(h+1) loads into same regs
            uint32_t* pA = (uint32_t*)(Asb + nxt * 128 * TS);
#pragma unroll
            for (int i = 0; i < 8; i++) {
                int f = tid + i * 256, r = f >> 4, c = (f & 15) << 2;
                uint32_t* p = pA + r * TS + c;
                p[0] = f2tf(rv[i].x); p[1] = f2tf(rv[i].y);
                p[2] = f2tf(rv[i].z); p[3] = f2tf(rv[i].w);
            }
            const float* Bn = B0 + (h + 1) * DH_;
#pragma unroll
            for (int i = 0; i < 8; i++) {
                int f = tid + i * 256, r = f >> 4, c = (f & 15) << 2;
                rv[i] = *(const float4*)(Bn + (size_t)(kb + r) * D_ + c);
            }
        }

        mma_range<32, 64>(Acur, Bcur, acc, wm, wn, lane);

        // epilogue: attn += exp(score)/ (16*s)
#pragma unroll
        for (int mi = 0; mi < 4; mi++) {
            int r0l = wm + mi * 16 + (lane >> 2);
            float i0 = sinv[h * 128 + r0l];
            float i1 = sinv[h * 128 + r0l + 8];
#pragma unroll
            for (int ni = 0; ni < 4; ni++) {
                attn[mi][ni][0] += __expf(acc[mi][ni][0] * 0.125f) * i0;
                attn[mi][ni][1] += __expf(acc[mi][ni][1] * 0.125f) * i0;
                attn[mi][ni][2] += __expf(acc[mi][ni][2] * 0.125f) * i1;
                attn[mi][ni][3] += __expf(acc[mi][ni][3] * 0.125f) * i1;
            }
        }

        if (h < 15) {  // store B(h+1)
            uint32_t* pB = (uint32_t*)(Bsb + nxt * 128 * TS);
#pragma unroll
            for (int i = 0; i < 8; i++) {
                int f = tid + i * 256, r = f >> 4, c = (f & 15) << 2;
                uint32_t* p = pB + r * TS + c;
                p[0] = f2tf(rv[i].x); p[1] = f2tf(rv[i].y);
                p[2] = f2tf(rv[i].z); p[3] = f2tf(rv[i].w);
            }
        }
        __syncthreads();
    }

    float* Crow = g_attn + ((size_t)b * Q_ + qb) * KV_ + kb;
#pragma unroll
    for (int mi = 0; mi < 4; mi++) {
        int r0 = wm + mi * 16 + (lane >> 2);
#pragma unroll
        for (int ni = 0; ni < 4; ni++) {
            int c0 = wn + ni * 8 + ((lane & 3) << 1);
            *(float2*)(Crow + (size_t)r0 * KV_ + c0)       = make_float2(attn[mi][ni][0], attn[mi][ni][1]);
            *(float2*)(Crow + (size_t)(r0 + 8) * KV_ + c0) = make_float2(attn[mi][ni][2], attn[mi][ni][3]);
        }
    }
}

// ---------------------------------------------------------------------------
// PV GEMM (NN): out = attn @ value. Batched over b.
// ---------------------------------------------------------------------------
__global__ __launch_bounds__(256) void gemm_nn_kernel(
    const float* __restrict__ A0, const float* __restrict__ B0, float* __restrict__ C0)
{
    __shared__ uint32_t As[128][BK + 4];
    __shared__ uint32_t Bs[BK][128 + 8];

    int z = blockIdx.z;
    const float* A  = A0 + (size_t)z * Q_ * KV_;
    const float* Bp = B0 + (size_t)z * KV_ * D_;
    float*       C  = C0 + (size_t)z * Q_ * D_;

    int bm = blockIdx.y * 128;
    int bn = blockIdx.x * 128;
    int tid = threadIdx.x, lane = tid & 31, wid = tid >> 5;
    int wm = (wid >> 2) * 64;
    int wn = (wid & 3) * 32;

    float acc[4][4][4];
#pragma unroll
    for (int mi = 0; mi < 4; mi++)
#pragma unroll
        for (int ni = 0; ni < 4; ni++)
#pragma unroll
            for (int c = 0; c < 4; c++) acc[mi][ni][c] = 0.0f;

    for (int kt = 0; kt < KV_; kt += BK) {
#pragma unroll
        for (int i = 0; i < 4; i++) {
            int f  = tid + i * 256;
            int ra  = f >> 3;
            int ca4 = (f & 7) << 2;
            float4 va = *(const float4*)(A + (size_t)(bm + ra) * KV_ + kt + ca4);
            As[ra][ca4]     = f2tf(va.x);
            As[ra][ca4 + 1] = f2tf(va.y);
            As[ra][ca4 + 2] = f2tf(va.z);
            As[ra][ca4 + 3] = f2tf(va.w);
            int rb  = f >> 5;
            int cb4 = (f & 31) << 2;
            float4 vb = *(const float4*)(Bp + (size_t)(kt + rb) * D_ + bn + cb4);
            Bs[rb][cb4]     = f2tf(vb.x);
            Bs[rb][cb4 + 1] = f2tf(vb.y);
            Bs[rb][cb4 + 2] = f2tf(vb.z);
            Bs[rb][cb4 + 3] = f2tf(vb.w);
        }
        __syncthreads();

#pragma unroll
        for (int kk = 0; kk < BK; kk += 8) {
            uint32_t af[4][4], bf[4][2];
            int c0 = kk + (lane & 3);
#pragma unroll
            for (int mi = 0; mi < 4; mi++) {
                int r0 = wm + mi * 16 + (lane >> 2);
                af[mi][0] = As[r0][c0];
                af[mi][1] = As[r0 + 8][c0];
                af[mi][2] = As[r0][c0 + 4];
                af[mi][3] = As[r0 + 8][c0 + 4];
            }
#pragma unroll
            for (int ni = 0; ni < 4; ni++) {
                int n0 = wn + ni * 8 + (lane >> 2);
                bf[ni][0] = Bs[kk + (lane & 3)][n0];
                bf[ni][1] = Bs[kk + (lane & 3) + 4][n0];
            }
#pragma unroll
            for (int mi = 0; mi < 4; mi++)
#pragma unroll
                for (int ni = 0; ni < 4; ni++)
                    mma8(acc[mi][ni], af[mi], bf[ni]);
        }
        __syncthreads();
    }

#pragma unroll
    for (int mi = 0; mi < 4; mi++) {
        int r0 = bm + wm + mi * 16 + (lane >> 2);
#pragma unroll
        for (int ni = 0; ni < 4; ni++) {
            int c0 = bn + wn + ni * 8 + ((lane & 3) << 1);
            C[(size_t)r0 * D_ + c0]           = acc[mi][ni][0];
            C[(size_t)r0 * D_ + c0 + 1]       = acc[mi][ni][1];
            C[(size_t)(r0 + 8) * D_ + c0]     = acc[mi][ni][2];
            C[(size_t)(r0 + 8) * D_ + c0 + 1] = acc[mi][ni][3];
        }
    }
}

// ---------------------------------------------------------------------------
// Host launcher
// ---------------------------------------------------------------------------
extern "C" void kernel_launch(void* const* d_in, const int* in_sizes, int n_in,
                              void* d_out, int out_size)
{
    (void)in_sizes; (void)n_in; (void)out_size;
    const float* query = (const float*)d_in[0];
    const float* key   = (const float*)d_in[1];
    const float* value = (const float*)d_in[2];
    const float* wqn   = (const float*)d_in[3];
    const float* wkn   = (const float*)d_in[4];
    const float* Wq    = (const float*)d_in[5];
    const float* Wk    = (const float*)d_in[6];
    const float* bq    = (const float*)d_in[7];
    const float* bk    = (const float*)d_in[8];
    float* out = (float*)d_out;

    float *qp, *kp, *attn, *rsc;
    cudaGetSymbolAddress((void**)&qp,   g_qp);
    cudaGetSymbolAddress((void**)&kp,   g_kp);
    cudaGetSymbolAddress((void**)&attn, g_attn);
    cudaGetSymbolAddress((void**)&rsc,  g_rscale);

    const int smem_k1 = (3 * 128 * TS + 128) * 4;
    const int smem_k2 = (4 * 128 * TS + 16 * 128) * 4;
    cudaFuncSetAttribute(k1_sumexp_kernel, cudaFuncAttributeMaxDynamicSharedMemorySize, smem_k1);
    cudaFuncSetAttribute(k2_attn_kernel,   cudaFuncAttributeMaxDynamicSharedMemorySize, smem_k2);

    // 1) per-row rmsnorm scales
    rms_scale_kernel<<<B_ * Q_ + B_ * KV_, 256>>>(query, key);

    // 2) Projections with fused rmsnorm
    dim3 gproj(D_ / 128, (B_ * Q_) / 128);   // (8, 32)
    gemm_proj_kernel<<<gproj, 256>>>(query, Wq, wqn, bq, rsc, qp);
    gemm_proj_kernel<<<gproj, 256>>>(key,   Wk, wkn, bk, rsc + B_ * Q_, kp);

    // 3) K1: per-(b,h,row) sumexp
    k1_sumexp_kernel<<<dim3(Q_ / 128, B_ * H_), 256, smem_k1>>>();

    // 4) K2: head-averaged attention probs -> g_attn
    k2_attn_kernel<<<dim3(KV_ / 128, Q_ / 128, B_), 256, smem_k2>>>();

    // 5) features = attn @ value -> d_out
    dim3 gpv(D_ / 128, Q_ / 128, B_);
    gemm_nn_kernel<<<gpv, 256>>>(attn, value, out);
}